// round 14
// baseline (speedup 1.0000x reference)
#include <cuda_runtime.h>
#include <cuda_fp16.h>
#include <math.h>
#include <stdint.h>

#define DM   1024
#define HD   64
#define NH   16
#define BATCH 2
#define SEQ  2048
#define NTOK (BATCH*SEQ)
#define MWORDS (BATCH*SEQ*SEQ/32)

// ---------------------------------------------------------------------------
// Scratch (no allocations allowed).  Pure fp16 pipeline.
// ---------------------------------------------------------------------------
__device__ __half g_iQ[NTOK*DM], g_iK[NTOK*DM], g_iV[NTOK*DM];
__device__ __half g_wq[DM*DM], g_wk[DM*DM], g_wv[DM*DM], g_wo[DM*DM];
__device__ __half g_Q[NTOK*DM], g_K[NTOK*DM], g_V[NTOK*DM];
__device__ __half g_O[NTOK*DM];
__device__ uint32_t g_Mb[MWORDS];

// ---------------------------------------------------------------------------
// Helpers
// ---------------------------------------------------------------------------
__device__ __forceinline__ uint32_t smem_u32(const void* p) {
    uint32_t a;
    asm("{ .reg .u64 t; cvta.to.shared.u64 t, %1; cvt.u32.u64 %0, t; }" : "=r"(a) : "l"(p));
    return a;
}
__device__ __forceinline__ uint32_t h2pack(float lo, float hi) {
    __half2 t = __floats2half2_rn(lo, hi);
    return *reinterpret_cast<uint32_t*>(&t);
}
__device__ __forceinline__ void ldm4(uint32_t* r, uint32_t addr) {
    asm volatile("ldmatrix.sync.aligned.m8n8.x4.shared.b16 {%0,%1,%2,%3}, [%4];"
                 : "=r"(r[0]), "=r"(r[1]), "=r"(r[2]), "=r"(r[3]) : "r"(addr));
}
__device__ __forceinline__ void ldm4t(uint32_t* r, uint32_t addr) {
    asm volatile("ldmatrix.sync.aligned.m8n8.x4.trans.shared.b16 {%0,%1,%2,%3}, [%4];"
                 : "=r"(r[0]), "=r"(r[1]), "=r"(r[2]), "=r"(r[3]) : "r"(addr));
}
__device__ __forceinline__ void mma16816(float* c, const uint32_t* a, const uint32_t* b) {
    asm volatile(
        "mma.sync.aligned.m16n8k16.row.col.f32.f16.f16.f32 "
        "{%0,%1,%2,%3}, {%4,%5,%6,%7}, {%8,%9}, {%0,%1,%2,%3};\n"
        : "+f"(c[0]), "+f"(c[1]), "+f"(c[2]), "+f"(c[3])
        : "r"(a[0]), "r"(a[1]), "r"(a[2]), "r"(a[3]), "r"(b[0]), "r"(b[1]));
}
__device__ __forceinline__ void cpa16(uint32_t dst, const void* src) {
    asm volatile("cp.async.cg.shared.global [%0], [%1], 16;" :: "r"(dst), "l"(src) : "memory");
}
__device__ __forceinline__ void cpa_commit() { asm volatile("cp.async.commit_group;" ::: "memory"); }
__device__ __forceinline__ void cpa_wait3()  { asm volatile("cp.async.wait_group 3;" ::: "memory"); }
__device__ __forceinline__ void cpa_wait2()  { asm volatile("cp.async.wait_group 2;" ::: "memory"); }
__device__ __forceinline__ void cpa_wait1()  { asm volatile("cp.async.wait_group 1;" ::: "memory"); }
__device__ __forceinline__ void cpa_wait0()  { asm volatile("cp.async.wait_group 0;" ::: "memory"); }

// ---------------------------------------------------------------------------
// Fused prep: 7 fp32->fp16 conversions (4 x float4 per thread, MLP=4)
// + mask bitpack, one launch.
// ---------------------------------------------------------------------------
#define IN_U  (NTOK*DM/4)            // 1048576 float4 units per input array
#define W_U   (DM*DM/4)              // 262144 per weight
#define CONV_UNITS (3*IN_U + 4*W_U)  // 4194304 (multiple of 4)
#define CONV_T (CONV_UNITS/4)        // 1048576 conv threads (mult of 256)
#define MASK_UNITS (BATCH*SEQ*SEQ/4) // 2097152 int4 units
#define PREP_BLOCKS ((CONV_T + MASK_UNITS) / 256)

__global__ __launch_bounds__(256) void prep_all(
    const float* __restrict__ q, const float* __restrict__ k,
    const float* __restrict__ v,
    const float* __restrict__ wq, const float* __restrict__ wk,
    const float* __restrict__ wv, const float* __restrict__ wo,
    const int* __restrict__ mask,
    __half* __restrict__ iQ, __half* __restrict__ iK, __half* __restrict__ iV,
    __half* __restrict__ wqh, __half* __restrict__ wkh,
    __half* __restrict__ wvh, __half* __restrict__ woh,
    uint32_t* __restrict__ bits) {
    int idx = blockIdx.x * 256 + threadIdx.x;
    if (idx < CONV_T) {
        int u0 = idx * 4;                 // first float4 unit of 4
        const float* src; __half* dst; int off;
        if (u0 < 3 * IN_U) {
            int arr = u0 >> 20;
            off = u0 & (IN_U - 1);
            src = arr == 0 ? q : arr == 1 ? k : v;
            dst = arr == 0 ? iQ : arr == 1 ? iK : iV;
        } else {
            int w = u0 - 3 * IN_U;
            int arr = w >> 18;
            off = w & (W_U - 1);
            src = arr == 0 ? wq : arr == 1 ? wk : arr == 2 ? wv : wo;
            dst = arr == 0 ? wqh : arr == 1 ? wkh : arr == 2 ? wvh : woh;
        }
        float4 a0 = ((const float4*)src)[off];
        float4 a1 = ((const float4*)src)[off + 1];
        float4 a2 = ((const float4*)src)[off + 2];
        float4 a3 = ((const float4*)src)[off + 3];
        ((uint2*)dst)[off]     = make_uint2(h2pack(a0.x, a0.y), h2pack(a0.z, a0.w));
        ((uint2*)dst)[off + 1] = make_uint2(h2pack(a1.x, a1.y), h2pack(a1.z, a1.w));
        ((uint2*)dst)[off + 2] = make_uint2(h2pack(a2.x, a2.y), h2pack(a2.z, a2.w));
        ((uint2*)dst)[off + 3] = make_uint2(h2pack(a3.x, a3.y), h2pack(a3.z, a3.w));
    } else {
        int t = idx - CONV_T;             // (t & 7) == (threadIdx.x & 7)
        int4 m = ((const int4*)mask)[t];
        uint32_t nib = (m.x != 0 ? 1u : 0u) | (m.y != 0 ? 2u : 0u) |
                       (m.z != 0 ? 4u : 0u) | (m.w != 0 ? 8u : 0u);
        uint32_t vv = nib << ((threadIdx.x & 7) * 4);
        vv |= __shfl_xor_sync(0xffffffffu, vv, 1);
        vv |= __shfl_xor_sync(0xffffffffu, vv, 2);
        vv |= __shfl_xor_sync(0xffffffffu, vv, 4);
        if ((threadIdx.x & 7) == 0) bits[t >> 3] = vv;
    }
}

// ---------------------------------------------------------------------------
// fp16 GEMM body (EXACT R10 champion config — frozen):
// Tile 128x128, BK=32, 5-stage cp.async pipeline, 4 warps (2m x 2n),
// warp tile 64x64 (32 MMAs per kk on 8 LDSM).
// MODE 1: fp16 C (scaled).  MODE 0: fp32 C.
// ---------------------------------------------------------------------------
#define LDSg 40                 // fp16 row stride (80B), conflict-free ldmatrix
#define PSTG (128*LDSg*2)       // 10240 B per plane
#define SSTG (2*PSTG)           // 20480 B per stage (A, B)
#define GNST 5
#define GDSM (GNST*SSTG)        // 102400 B dynamic smem

template<int MODE>
__device__ __forceinline__ void gemm_body(const __half* __restrict__ A,
                                          const __half* __restrict__ B,
                                          float* __restrict__ C,
                                          __half* __restrict__ Ch, float scale) {
    extern __shared__ char dsm[];
    const uint32_t base = smem_u32(dsm);
    const int tid = threadIdx.x, lane = tid & 31, warp = tid >> 5;
    const int wm = (warp & 1) * 64;
    const int wn = (warp >> 1) * 64;
    const int bm = blockIdx.y * 128;
    const int bn = blockIdx.x * 128;

    const __half* gp[2] = { A + (size_t)bm * DM, B + (size_t)bn * DM };

    float acc[4][8][4];
#pragma unroll
    for (int i = 0; i < 4; i++)
#pragma unroll
        for (int j = 0; j < 8; j++)
#pragma unroll
            for (int v = 0; v < 4; v++) acc[i][j][v] = 0.f;

    // Stage load: 2 planes x 128 rows x 4 x 16B chunks = 1024 chunks, 8/thread.
#define G_LOAD(s, k0)                                                           \
    {                                                                           \
        uint32_t sb = base + (uint32_t)(s) * SSTG;                              \
        _Pragma("unroll")                                                       \
        for (int i = 0; i < 8; i++) {                                           \
            int id = tid + i * 128;                                             \
            int pl = id >> 9, cid = id & 511;                                   \
            int r = cid >> 2, ch = cid & 3;                                     \
            cpa16(sb + pl * PSTG + r * (LDSg * 2) + ch * 16,                    \
                  gp[pl] + (size_t)r * DM + (k0) + ch * 8);                     \
        }                                                                       \
        cpa_commit();                                                           \
    }

    G_LOAD(0, 0);
    G_LOAD(1, 32);
    G_LOAD(2, 64);
    G_LOAD(3, 96);

    for (int kt = 0; kt < 32; kt++) {
        int rem = 31 - kt;
        if (rem >= 3)      cpa_wait3();
        else if (rem == 2) cpa_wait2();
        else if (rem == 1) cpa_wait1();
        else               cpa_wait0();
        __syncthreads();
        if (kt + 4 < 32) G_LOAD((kt + 4) % GNST, (kt + 4) * 32);

        const uint32_t sb = base + (uint32_t)(kt % GNST) * SSTG;
        const uint32_t sA = sb, sB = sb + PSTG;

#pragma unroll
        for (int kk = 0; kk < 2; kk++) {
            uint32_t ah[4][4], bh[4][4];
            const int acol = kk * 16 + (lane >> 4) * 8;
#pragma unroll
            for (int i = 0; i < 4; i++) {
                int arow = wm + i * 16 + (lane & 15);
                ldm4(ah[i], sA + (uint32_t)arow * (LDSg * 2) + acol * 2);
            }
            const int bcol = kk * 16 + ((lane >> 3) & 1) * 8;
            const int brow_off = (lane & 7) + (lane >> 4) * 8;
#pragma unroll
            for (int j2 = 0; j2 < 4; j2++) {
                int brow = wn + j2 * 16 + brow_off;
                ldm4(bh[j2], sB + (uint32_t)brow * (LDSg * 2) + bcol * 2);
            }
#pragma unroll
            for (int i = 0; i < 4; i++)
#pragma unroll
                for (int j = 0; j < 8; j++)
                    mma16816(acc[i][j], ah[i], &bh[j >> 1][(j & 1) * 2]);
        }
    }

    const int g  = lane >> 2;
    const int t2 = (lane & 3) * 2;
#pragma unroll
    for (int i = 0; i < 4; i++)
#pragma unroll
        for (int j = 0; j < 8; j++) {
            int row = bm + wm + i * 16 + g;
            int col = bn + wn + j * 8 + t2;
            size_t i0 = (size_t)row * DM + col;
            size_t i1 = (size_t)(row + 8) * DM + col;
            float v0 = acc[i][j][0] * scale, v1 = acc[i][j][1] * scale;
            float v2 = acc[i][j][2] * scale, v3 = acc[i][j][3] * scale;
            if (MODE == 0) {
                *(float2*)(C + i0) = make_float2(v0, v1);
                *(float2*)(C + i1) = make_float2(v2, v3);
            } else {
                *(uint32_t*)(Ch + i0) = h2pack(v0, v1);
                *(uint32_t*)(Ch + i1) = h2pack(v2, v3);
            }
        }
#undef G_LOAD
}

// Batched projection GEMM (z = 0:Q, 1:K, 2:V) and output GEMM.
__global__ __launch_bounds__(128, 2) void gemm_proj(
    const __half* __restrict__ iQ, const __half* __restrict__ iK,
    const __half* __restrict__ iV,
    const __half* __restrict__ wq, const __half* __restrict__ wk,
    const __half* __restrict__ wv,
    __half* __restrict__ Qo, __half* __restrict__ Ko, __half* __restrict__ Vo) {
    const __half* A; const __half* B; __half* Ch; float scale = 1.0f;
    if (blockIdx.z == 0)      { A = iQ; B = wq; Ch = Qo; scale = 0.125f; }
    else if (blockIdx.z == 1) { A = iK; B = wk; Ch = Ko; }
    else                      { A = iV; B = wv; Ch = Vo; }
    gemm_body<1>(A, B, nullptr, Ch, scale);
}
__global__ __launch_bounds__(128, 2) void gemm_out(
    const __half* __restrict__ O, const __half* __restrict__ wo,
    float* __restrict__ out) {
    gemm_body<0>(O, wo, out, nullptr, 1.0f);
}

// ---------------------------------------------------------------------------
// fp16 flash attention.  128 q-rows per CTA (two 64-row subtiles sharing the
// staged K/V fragments), 4 warps.  K/V pipeline upgraded to the R10-validated
// GEMM schedule: 5 stages, prefetch 4, wait_group 3/2/1/0 ladder.
// Q pre-scaled by 1/8.
// ---------------------------------------------------------------------------
#define LDA 72                   // fp16 row stride (144B), conflict-free
#define APLN (64*LDA*2)          // 9216 B per plane
#define ASTG (2*APLN)            // 18432 B per stage (K, V)
#define ANST 5
#define ADSM (ANST*ASTG)         // 92160 B dynamic smem (5 stages)
#define NKT  (SEQ/64)            // 32

__global__ __launch_bounds__(128, 2) void attn_fp16(
    const __half* __restrict__ Q, const __half* __restrict__ K,
    const __half* __restrict__ V, const uint32_t* __restrict__ Mb,
    __half* __restrict__ O) {
    extern __shared__ char dsm[];
    const uint32_t base = smem_u32(dsm);

    const int b = blockIdx.z, h = blockIdx.y;
    const int q0 = blockIdx.x * 128;
    const int tid = threadIdx.x, lane = tid & 31, warp = tid >> 5;
    const int g = lane >> 2, t2 = (lane & 3) * 2;

    // Prologue: stage 128 Q rows (occupies stage-0/1 area), read A fragments.
    {
        __half* sQ = (__half*)(dsm);
        for (int idx = tid; idx < 1024; idx += 128) {
            int r = idx >> 3, c = (idx & 7) * 8;
            size_t go = (size_t)(b * SEQ + q0 + r) * DM + h * HD + c;
            *(uint4*)(sQ + r * LDA + c) = *(const uint4*)(Q + go);
        }
    }
    __syncthreads();
    uint32_t qh[2][4][4];
#pragma unroll
    for (int t = 0; t < 2; t++) {
        int arow = t * 64 + warp * 16 + (lane & 15);
#pragma unroll
        for (int kk = 0; kk < 4; kk++) {
            int acol = kk * 16 + (lane >> 4) * 8;
            ldm4(qh[t][kk], base + (uint32_t)arow * (LDA * 2) + acol * 2);
        }
    }
    __syncthreads();

#define A_LOAD(s, kt)                                                           \
    {                                                                           \
        uint32_t sb = base + (uint32_t)(s) * ASTG;                              \
        const __half* gsrc[2] = { K, V };                                       \
        _Pragma("unroll")                                                       \
        for (int i = 0; i < 8; i++) {                                           \
            int id = tid + i * 128;                                             \
            int ar = id >> 9, cid = id & 511;                                   \
            int r = cid >> 3, ch = cid & 7;                                     \
            cpa16(sb + ar * APLN + r * (LDA * 2) + ch * 16,                     \
                  gsrc[ar] + (size_t)(b * SEQ + (kt) * 64 + r) * DM + h * HD + ch * 8); \
        }                                                                       \
        cpa_commit();                                                           \
    }

    float oa[2][8][4];
#pragma unroll
    for (int t = 0; t < 2; t++)
#pragma unroll
        for (int j = 0; j < 8; j++)
#pragma unroll
            for (int v = 0; v < 4; v++) oa[t][j][v] = 0.f;
    float mx[2][2] = {{-INFINITY, -INFINITY}, {-INFINITY, -INFINITY}};
    float ll[2][2] = {{0.f, 0.f}, {0.f, 0.f}};

    const uint32_t* mr[2][2];
#pragma unroll
    for (int t = 0; t < 2; t++) {
        mr[t][0] = Mb + (size_t)(b * SEQ + q0 + t * 64 + warp * 16 + g) * (SEQ / 32);
        mr[t][1] = mr[t][0] + 8 * (SEQ / 32);
    }

    A_LOAD(0, 0);
    A_LOAD(1, 1);
    A_LOAD(2, 2);
    A_LOAD(3, 3);

    for (int kt = 0; kt < NKT; kt++) {
        int rem = NKT - 1 - kt;
        if (rem >= 3)      cpa_wait3();
        else if (rem == 2) cpa_wait2();
        else if (rem == 1) cpa_wait1();
        else               cpa_wait0();
        __syncthreads();
        if (kt + 4 < NKT) A_LOAD((kt + 4) % ANST, kt + 4);

        const uint32_t sK = base + (uint32_t)(kt % ANST) * ASTG;
        const uint32_t sV = sK + APLN;

        // S = Q K^T for both subtiles, sharing K fragments.
        float s[2][8][4];
#pragma unroll
        for (int t = 0; t < 2; t++)
#pragma unroll
            for (int j = 0; j < 8; j++)
#pragma unroll
                for (int v = 0; v < 4; v++) s[t][j][v] = 0.f;
#pragma unroll
        for (int kk = 0; kk < 4; kk++) {
            uint32_t bh[4][4];
            const int bro = (lane & 7) + (lane >> 4) * 8;
            const int bco = kk * 16 + ((lane >> 3) & 1) * 8;
#pragma unroll
            for (int j2 = 0; j2 < 4; j2++)
                ldm4(bh[j2], sK + (uint32_t)(j2 * 16 + bro) * (LDA * 2) + bco * 2);
#pragma unroll
            for (int t = 0; t < 2; t++)
#pragma unroll
                for (int j = 0; j < 8; j++)
                    mma16816(s[t][j], qh[t][kk], &bh[j >> 1][(j & 1) * 2]);
        }

        // Mask + online softmax + P repack per subtile.
        uint32_t ph[2][4][4];
#pragma unroll
        for (int t = 0; t < 2; t++) {
            uint32_t w0a = mr[t][0][kt * 2], w0b = mr[t][0][kt * 2 + 1];
            uint32_t w1a = mr[t][1][kt * 2], w1b = mr[t][1][kt * 2 + 1];
#pragma unroll
            for (int j = 0; j < 8; j++) {
                uint32_t wr0 = (j < 4) ? w0a : w0b;
                uint32_t wr1 = (j < 4) ? w1a : w1b;
                int sh = (j * 8 + t2) & 31;
                if (!((wr0 >> sh) & 1u))       s[t][j][0] = -1e20f;
                if (!((wr0 >> (sh + 1)) & 1u)) s[t][j][1] = -1e20f;
                if (!((wr1 >> sh) & 1u))       s[t][j][2] = -1e20f;
                if (!((wr1 >> (sh + 1)) & 1u)) s[t][j][3] = -1e20f;
            }

            float tm0 = s[t][0][0], tm1 = s[t][0][2];
#pragma unroll
            for (int j = 0; j < 8; j++) {
                tm0 = fmaxf(tm0, fmaxf(s[t][j][0], s[t][j][1]));
                tm1 = fmaxf(tm1, fmaxf(s[t][j][2], s[t][j][3]));
            }
            tm0 = fmaxf(tm0, __shfl_xor_sync(0xffffffffu, tm0, 1));
            tm0 = fmaxf(tm0, __shfl_xor_sync(0xffffffffu, tm0, 2));
            tm1 = fmaxf(tm1, __shfl_xor_sync(0xffffffffu, tm1, 1));
            tm1 = fmaxf(tm1, __shfl_xor_sync(0xffffffffu, tm1, 2));
            float nm0 = fmaxf(mx[t][0], tm0), nm1 = fmaxf(mx[t][1], tm1);
            float cr0 = __expf(mx[t][0] - nm0), cr1 = __expf(mx[t][1] - nm1);
            mx[t][0] = nm0; mx[t][1] = nm1;

            float ps0 = 0.f, ps1 = 0.f;
#pragma unroll
            for (int j = 0; j < 8; j++) {
                s[t][j][0] = __expf(s[t][j][0] - nm0); ps0 += s[t][j][0];
                s[t][j][1] = __expf(s[t][j][1] - nm0); ps0 += s[t][j][1];
                s[t][j][2] = __expf(s[t][j][2] - nm1); ps1 += s[t][j][2];
                s[t][j][3] = __expf(s[t][j][3] - nm1); ps1 += s[t][j][3];
            }
            ps0 += __shfl_xor_sync(0xffffffffu, ps0, 1);
            ps0 += __shfl_xor_sync(0xffffffffu, ps0, 2);
            ps1 += __shfl_xor_sync(0xffffffffu, ps1, 1);
            ps1 += __shfl_xor_sync(0xffffffffu, ps1, 2);
            ll[t][0] = ll[t][0] * cr0 + ps0;
            ll[t][1] = ll[t][1] * cr1 + ps1;
#pragma unroll
            for (int j = 0; j < 8; j++) {
                oa[t][j][0] *= cr0; oa[t][j][1] *= cr0;
                oa[t][j][2] *= cr1; oa[t][j][3] *= cr1;
            }
#pragma unroll
            for (int s4 = 0; s4 < 4; s4++) {
                int ta = 2 * s4, tb = ta + 1;
                ph[t][s4][0] = h2pack(s[t][ta][0], s[t][ta][1]);
                ph[t][s4][1] = h2pack(s[t][ta][2], s[t][ta][3]);
                ph[t][s4][2] = h2pack(s[t][tb][0], s[t][tb][1]);
                ph[t][s4][3] = h2pack(s[t][tb][2], s[t][tb][3]);
            }
        }

        // O += P V for both subtiles, sharing V fragments.
#pragma unroll
        for (int s4 = 0; s4 < 4; s4++) {
            uint32_t vh[4][4];
            const int vrow = s4 * 16 + ((lane >> 3) & 1) * 8 + (lane & 7);
#pragma unroll
            for (int n2 = 0; n2 < 4; n2++) {
                int vcol = n2 * 16 + (lane >> 4) * 8;
                ldm4t(vh[n2], sV + (uint32_t)vrow * (LDA * 2) + vcol * 2);
            }
#pragma unroll
            for (int t = 0; t < 2; t++)
#pragma unroll
                for (int j = 0; j < 8; j++)
                    mma16816(oa[t][j], ph[t][s4], &vh[j >> 1][(j & 1) * 2]);
        }
    }

#pragma unroll
    for (int t = 0; t < 2; t++) {
        float il0 = 1.f / ll[t][0], il1 = 1.f / ll[t][1];
        int row0 = b * SEQ + q0 + t * 64 + warp * 16 + g;
        size_t b0 = (size_t)row0 * DM + h * HD;
        size_t b1 = b0 + (size_t)8 * DM;
#pragma unroll
        for (int j = 0; j < 8; j++) {
            *(uint32_t*)(O + b0 + j * 8 + t2) = h2pack(oa[t][j][0] * il0, oa[t][j][1] * il0);
            *(uint32_t*)(O + b1 + j * 8 + t2) = h2pack(oa[t][j][2] * il1, oa[t][j][3] * il1);
        }
    }
#undef A_LOAD
}

// ---------------------------------------------------------------------------
extern "C" void kernel_launch(void* const* d_in, const int* in_sizes, int n_in,
                              void* d_out, int out_size) {
    const float* query = (const float*)d_in[0];
    const float* key_t = (const float*)d_in[1];
    const float* value = (const float*)d_in[2];
    const int*   mask  = (const int*)d_in[3];
    const float* wq    = (const float*)d_in[4];
    const float* wk    = (const float*)d_in[5];
    const float* wv    = (const float*)d_in[6];
    const float* wo    = (const float*)d_in[7];
    float* out = (float*)d_out;

    __half *iQ, *iK, *iV, *wqh, *wkh, *wvh, *woh, *Qp, *Kp, *Vp, *Op;
    uint32_t* Mb;
    cudaGetSymbolAddress((void**)&iQ, g_iQ);   cudaGetSymbolAddress((void**)&iK, g_iK);
    cudaGetSymbolAddress((void**)&iV, g_iV);
    cudaGetSymbolAddress((void**)&wqh, g_wq);  cudaGetSymbolAddress((void**)&wkh, g_wk);
    cudaGetSymbolAddress((void**)&wvh, g_wv);  cudaGetSymbolAddress((void**)&woh, g_wo);
    cudaGetSymbolAddress((void**)&Qp, g_Q);    cudaGetSymbolAddress((void**)&Kp, g_K);
    cudaGetSymbolAddress((void**)&Vp, g_V);    cudaGetSymbolAddress((void**)&Op, g_O);
    cudaGetSymbolAddress((void**)&Mb, g_Mb);

    static bool attr_set = false;
    if (!attr_set) {
        cudaFuncSetAttribute(gemm_proj, cudaFuncAttributeMaxDynamicSharedMemorySize, GDSM);
        cudaFuncSetAttribute(gemm_out,  cudaFuncAttributeMaxDynamicSharedMemorySize, GDSM);
        cudaFuncSetAttribute(attn_fp16, cudaFuncAttributeMaxDynamicSharedMemorySize, ADSM);
        attr_set = true;
    }

    prep_all<<<PREP_BLOCKS, 256>>>(query, key_t, value, wq, wk, wv, wo, mask,
                                   iQ, iK, iV, wqh, wkh, wvh, woh, Mb);

    dim3 gp3(DM / 128, NTOK / 128, 3);   // (8, 32, 3)
    gemm_proj<<<gp3, 128, GDSM>>>(iQ, iK, iV, wqh, wkh, wvh, Qp, Kp, Vp);

    dim3 ga(SEQ / 128, NH, BATCH);       // (16, 16, 2)
    attn_fp16<<<ga, 128, ADSM>>>(Qp, Kp, Vp, Mb, Op);

    dim3 gg(DM / 128, NTOK / 128);       // (8, 32)
    gemm_out<<<gg, 128, GDSM>>>(Op, woh, out);
}

// round 16
// speedup vs baseline: 1.0557x; 1.0557x over previous
#include <cuda_runtime.h>
#include <cuda_fp16.h>
#include <math.h>
#include <stdint.h>

#define DM   1024
#define HD   64
#define NH   16
#define BATCH 2
#define SEQ  2048
#define NTOK (BATCH*SEQ)
#define MWORDS (BATCH*SEQ*SEQ/32)

// ---------------------------------------------------------------------------
// Scratch (no allocations allowed).  Pure fp16 pipeline.
// ---------------------------------------------------------------------------
__device__ __half g_iQ[NTOK*DM], g_iK[NTOK*DM], g_iV[NTOK*DM];
__device__ __half g_wq[DM*DM], g_wk[DM*DM], g_wv[DM*DM], g_wo[DM*DM];
__device__ __half g_Q[NTOK*DM], g_K[NTOK*DM], g_V[NTOK*DM];
__device__ __half g_O[NTOK*DM];
__device__ uint32_t g_Mb[MWORDS];

// ---------------------------------------------------------------------------
// Helpers
// ---------------------------------------------------------------------------
__device__ __forceinline__ uint32_t smem_u32(const void* p) {
    uint32_t a;
    asm("{ .reg .u64 t; cvta.to.shared.u64 t, %1; cvt.u32.u64 %0, t; }" : "=r"(a) : "l"(p));
    return a;
}
__device__ __forceinline__ uint32_t h2pack(float lo, float hi) {
    __half2 t = __floats2half2_rn(lo, hi);
    return *reinterpret_cast<uint32_t*>(&t);
}
__device__ __forceinline__ float ex2f(float x) {
    float y;
    asm("ex2.approx.ftz.f32 %0, %1;" : "=f"(y) : "f"(x));
    return y;
}
__device__ __forceinline__ void ldm4(uint32_t* r, uint32_t addr) {
    asm volatile("ldmatrix.sync.aligned.m8n8.x4.shared.b16 {%0,%1,%2,%3}, [%4];"
                 : "=r"(r[0]), "=r"(r[1]), "=r"(r[2]), "=r"(r[3]) : "r"(addr));
}
__device__ __forceinline__ void ldm4t(uint32_t* r, uint32_t addr) {
    asm volatile("ldmatrix.sync.aligned.m8n8.x4.trans.shared.b16 {%0,%1,%2,%3}, [%4];"
                 : "=r"(r[0]), "=r"(r[1]), "=r"(r[2]), "=r"(r[3]) : "r"(addr));
}
__device__ __forceinline__ void mma16816(float* c, const uint32_t* a, const uint32_t* b) {
    asm volatile(
        "mma.sync.aligned.m16n8k16.row.col.f32.f16.f16.f32 "
        "{%0,%1,%2,%3}, {%4,%5,%6,%7}, {%8,%9}, {%0,%1,%2,%3};\n"
        : "+f"(c[0]), "+f"(c[1]), "+f"(c[2]), "+f"(c[3])
        : "r"(a[0]), "r"(a[1]), "r"(a[2]), "r"(a[3]), "r"(b[0]), "r"(b[1]));
}
__device__ __forceinline__ void cpa16(uint32_t dst, const void* src) {
    asm volatile("cp.async.cg.shared.global [%0], [%1], 16;" :: "r"(dst), "l"(src) : "memory");
}
__device__ __forceinline__ void cpa_commit() { asm volatile("cp.async.commit_group;" ::: "memory"); }
__device__ __forceinline__ void cpa_wait3()  { asm volatile("cp.async.wait_group 3;" ::: "memory"); }
__device__ __forceinline__ void cpa_wait2()  { asm volatile("cp.async.wait_group 2;" ::: "memory"); }
__device__ __forceinline__ void cpa_wait1()  { asm volatile("cp.async.wait_group 1;" ::: "memory"); }
__device__ __forceinline__ void cpa_wait0()  { asm volatile("cp.async.wait_group 0;" ::: "memory"); }

// ---------------------------------------------------------------------------
// Fused prep: 7 fp32->fp16 conversions (4 x float4 per thread, MLP=4)
// + mask bitpack, one launch.
// ---------------------------------------------------------------------------
#define IN_U  (NTOK*DM/4)            // 1048576 float4 units per input array
#define W_U   (DM*DM/4)              // 262144 per weight
#define CONV_UNITS (3*IN_U + 4*W_U)  // 4194304 (multiple of 4)
#define CONV_T (CONV_UNITS/4)        // 1048576 conv threads (mult of 256)
#define MASK_UNITS (BATCH*SEQ*SEQ/4) // 2097152 int4 units
#define PREP_BLOCKS ((CONV_T + MASK_UNITS) / 256)

__global__ __launch_bounds__(256) void prep_all(
    const float* __restrict__ q, const float* __restrict__ k,
    const float* __restrict__ v,
    const float* __restrict__ wq, const float* __restrict__ wk,
    const float* __restrict__ wv, const float* __restrict__ wo,
    const int* __restrict__ mask,
    __half* __restrict__ iQ, __half* __restrict__ iK, __half* __restrict__ iV,
    __half* __restrict__ wqh, __half* __restrict__ wkh,
    __half* __restrict__ wvh, __half* __restrict__ woh,
    uint32_t* __restrict__ bits) {
    int idx = blockIdx.x * 256 + threadIdx.x;
    if (idx < CONV_T) {
        int u0 = idx * 4;                 // first float4 unit of 4
        const float* src; __half* dst; int off;
        if (u0 < 3 * IN_U) {
            int arr = u0 >> 20;
            off = u0 & (IN_U - 1);
            src = arr == 0 ? q : arr == 1 ? k : v;
            dst = arr == 0 ? iQ : arr == 1 ? iK : iV;
        } else {
            int w = u0 - 3 * IN_U;
            int arr = w >> 18;
            off = w & (W_U - 1);
            src = arr == 0 ? wq : arr == 1 ? wk : arr == 2 ? wv : wo;
            dst = arr == 0 ? wqh : arr == 1 ? wkh : arr == 2 ? wvh : woh;
        }
        float4 a0 = ((const float4*)src)[off];
        float4 a1 = ((const float4*)src)[off + 1];
        float4 a2 = ((const float4*)src)[off + 2];
        float4 a3 = ((const float4*)src)[off + 3];
        ((uint2*)dst)[off]     = make_uint2(h2pack(a0.x, a0.y), h2pack(a0.z, a0.w));
        ((uint2*)dst)[off + 1] = make_uint2(h2pack(a1.x, a1.y), h2pack(a1.z, a1.w));
        ((uint2*)dst)[off + 2] = make_uint2(h2pack(a2.x, a2.y), h2pack(a2.z, a2.w));
        ((uint2*)dst)[off + 3] = make_uint2(h2pack(a3.x, a3.y), h2pack(a3.z, a3.w));
    } else {
        int t = idx - CONV_T;             // (t & 7) == (threadIdx.x & 7)
        int4 m = ((const int4*)mask)[t];
        uint32_t nib = (m.x != 0 ? 1u : 0u) | (m.y != 0 ? 2u : 0u) |
                       (m.z != 0 ? 4u : 0u) | (m.w != 0 ? 8u : 0u);
        uint32_t vv = nib << ((threadIdx.x & 7) * 4);
        vv |= __shfl_xor_sync(0xffffffffu, vv, 1);
        vv |= __shfl_xor_sync(0xffffffffu, vv, 2);
        vv |= __shfl_xor_sync(0xffffffffu, vv, 4);
        if ((threadIdx.x & 7) == 0) bits[t >> 3] = vv;
    }
}

// ---------------------------------------------------------------------------
// fp16 GEMM body (EXACT R10 champion config — frozen):
// Tile 128x128, BK=32, 5-stage cp.async pipeline, 4 warps (2m x 2n),
// warp tile 64x64 (32 MMAs per kk on 8 LDSM).
// MODE 1: fp16 C (scaled).  MODE 0: fp32 C.
// ---------------------------------------------------------------------------
#define LDSg 40                 // fp16 row stride (80B), conflict-free ldmatrix
#define PSTG (128*LDSg*2)       // 10240 B per plane
#define SSTG (2*PSTG)           // 20480 B per stage (A, B)
#define GNST 5
#define GDSM (GNST*SSTG)        // 102400 B dynamic smem

template<int MODE>
__device__ __forceinline__ void gemm_body(const __half* __restrict__ A,
                                          const __half* __restrict__ B,
                                          float* __restrict__ C,
                                          __half* __restrict__ Ch, float scale) {
    extern __shared__ char dsm[];
    const uint32_t base = smem_u32(dsm);
    const int tid = threadIdx.x, lane = tid & 31, warp = tid >> 5;
    const int wm = (warp & 1) * 64;
    const int wn = (warp >> 1) * 64;
    const int bm = blockIdx.y * 128;
    const int bn = blockIdx.x * 128;

    const __half* gp[2] = { A + (size_t)bm * DM, B + (size_t)bn * DM };

    float acc[4][8][4];
#pragma unroll
    for (int i = 0; i < 4; i++)
#pragma unroll
        for (int j = 0; j < 8; j++)
#pragma unroll
            for (int v = 0; v < 4; v++) acc[i][j][v] = 0.f;

    // Stage load: 2 planes x 128 rows x 4 x 16B chunks = 1024 chunks, 8/thread.
#define G_LOAD(s, k0)                                                           \
    {                                                                           \
        uint32_t sb = base + (uint32_t)(s) * SSTG;                              \
        _Pragma("unroll")                                                       \
        for (int i = 0; i < 8; i++) {                                           \
            int id = tid + i * 128;                                             \
            int pl = id >> 9, cid = id & 511;                                   \
            int r = cid >> 2, ch = cid & 3;                                     \
            cpa16(sb + pl * PSTG + r * (LDSg * 2) + ch * 16,                    \
                  gp[pl] + (size_t)r * DM + (k0) + ch * 8);                     \
        }                                                                       \
        cpa_commit();                                                           \
    }

    G_LOAD(0, 0);
    G_LOAD(1, 32);
    G_LOAD(2, 64);
    G_LOAD(3, 96);

    for (int kt = 0; kt < 32; kt++) {
        int rem = 31 - kt;
        if (rem >= 3)      cpa_wait3();
        else if (rem == 2) cpa_wait2();
        else if (rem == 1) cpa_wait1();
        else               cpa_wait0();
        __syncthreads();
        if (kt + 4 < 32) G_LOAD((kt + 4) % GNST, (kt + 4) * 32);

        const uint32_t sb = base + (uint32_t)(kt % GNST) * SSTG;
        const uint32_t sA = sb, sB = sb + PSTG;

#pragma unroll
        for (int kk = 0; kk < 2; kk++) {
            uint32_t ah[4][4], bh[4][4];
            const int acol = kk * 16 + (lane >> 4) * 8;
#pragma unroll
            for (int i = 0; i < 4; i++) {
                int arow = wm + i * 16 + (lane & 15);
                ldm4(ah[i], sA + (uint32_t)arow * (LDSg * 2) + acol * 2);
            }
            const int bcol = kk * 16 + ((lane >> 3) & 1) * 8;
            const int brow_off = (lane & 7) + (lane >> 4) * 8;
#pragma unroll
            for (int j2 = 0; j2 < 4; j2++) {
                int brow = wn + j2 * 16 + brow_off;
                ldm4(bh[j2], sB + (uint32_t)brow * (LDSg * 2) + bcol * 2);
            }
#pragma unroll
            for (int i = 0; i < 4; i++)
#pragma unroll
                for (int j = 0; j < 8; j++)
                    mma16816(acc[i][j], ah[i], &bh[j >> 1][(j & 1) * 2]);
        }
    }

    const int g  = lane >> 2;
    const int t2 = (lane & 3) * 2;
#pragma unroll
    for (int i = 0; i < 4; i++)
#pragma unroll
        for (int j = 0; j < 8; j++) {
            int row = bm + wm + i * 16 + g;
            int col = bn + wn + j * 8 + t2;
            size_t i0 = (size_t)row * DM + col;
            size_t i1 = (size_t)(row + 8) * DM + col;
            float v0 = acc[i][j][0] * scale, v1 = acc[i][j][1] * scale;
            float v2 = acc[i][j][2] * scale, v3 = acc[i][j][3] * scale;
            if (MODE == 0) {
                *(float2*)(C + i0) = make_float2(v0, v1);
                *(float2*)(C + i1) = make_float2(v2, v3);
            } else {
                *(uint32_t*)(Ch + i0) = h2pack(v0, v1);
                *(uint32_t*)(Ch + i1) = h2pack(v2, v3);
            }
        }
#undef G_LOAD
}

// Batched projection GEMM (z = 0:Q, 1:K, 2:V) and output GEMM.
// Q is pre-scaled by (1/8)*log2(e): attention scores land in the log2 domain,
// so softmax uses bare ex2.approx (no per-element FMUL by log2e).
__global__ __launch_bounds__(128, 2) void gemm_proj(
    const __half* __restrict__ iQ, const __half* __restrict__ iK,
    const __half* __restrict__ iV,
    const __half* __restrict__ wq, const __half* __restrict__ wk,
    const __half* __restrict__ wv,
    __half* __restrict__ Qo, __half* __restrict__ Ko, __half* __restrict__ Vo) {
    const __half* A; const __half* B; __half* Ch; float scale = 1.0f;
    if (blockIdx.z == 0)      { A = iQ; B = wq; Ch = Qo; scale = 0.125f * 1.44269504f; }
    else if (blockIdx.z == 1) { A = iK; B = wk; Ch = Ko; }
    else                      { A = iV; B = wv; Ch = Vo; }
    gemm_body<1>(A, B, nullptr, Ch, scale);
}
__global__ __launch_bounds__(128, 2) void gemm_out(
    const __half* __restrict__ O, const __half* __restrict__ wo,
    float* __restrict__ out) {
    gemm_body<0>(O, wo, out, nullptr, 1.0f);
}

// ---------------------------------------------------------------------------
// fp16 flash attention, ONLINE softmax in the log2 domain.
// Scores are already scaled by log2(e)/8; max-tracking/correction identical in
// structure to the R10 champion, but every exp is a bare ex2.approx.
// 128 q-rows per CTA, 4 warps, 4-stage cp.async K/V pipeline.
// ---------------------------------------------------------------------------
#define LDA 72                   // fp16 row stride (144B), conflict-free
#define APLN (64*LDA*2)          // 9216 B per plane
#define ASTG (2*APLN)            // 18432 B per stage (K, V)
#define ADSM (4*ASTG)            // 73728 B dynamic smem (4 stages)
#define NKT  (SEQ/64)            // 32

__global__ __launch_bounds__(128, 2) void attn_fp16(
    const __half* __restrict__ Q, const __half* __restrict__ K,
    const __half* __restrict__ V, const uint32_t* __restrict__ Mb,
    __half* __restrict__ O) {
    extern __shared__ char dsm[];
    const uint32_t base = smem_u32(dsm);

    const int b = blockIdx.z, h = blockIdx.y;
    const int q0 = blockIdx.x * 128;
    const int tid = threadIdx.x, lane = tid & 31, warp = tid >> 5;
    const int g = lane >> 2, t2 = (lane & 3) * 2;

    {
        __half* sQ = (__half*)(dsm);
        for (int idx = tid; idx < 1024; idx += 128) {
            int r = idx >> 3, c = (idx & 7) * 8;
            size_t go = (size_t)(b * SEQ + q0 + r) * DM + h * HD + c;
            *(uint4*)(sQ + r * LDA + c) = *(const uint4*)(Q + go);
        }
    }
    __syncthreads();
    uint32_t qh[2][4][4];
#pragma unroll
    for (int t = 0; t < 2; t++) {
        int arow = t * 64 + warp * 16 + (lane & 15);
#pragma unroll
        for (int kk = 0; kk < 4; kk++) {
            int acol = kk * 16 + (lane >> 4) * 8;
            ldm4(qh[t][kk], base + (uint32_t)arow * (LDA * 2) + acol * 2);
        }
    }
    __syncthreads();

#define A_LOAD(s, kt)                                                           \
    {                                                                           \
        uint32_t sb = base + (uint32_t)(s) * ASTG;                              \
        const __half* gsrc[2] = { K, V };                                       \
        _Pragma("unroll")                                                       \
        for (int i = 0; i < 8; i++) {                                           \
            int id = tid + i * 128;                                             \
            int ar = id >> 9, cid = id & 511;                                   \
            int r = cid >> 3, ch = cid & 7;                                     \
            cpa16(sb + ar * APLN + r * (LDA * 2) + ch * 16,                     \
                  gsrc[ar] + (size_t)(b * SEQ + (kt) * 64 + r) * DM + h * HD + ch * 8); \
        }                                                                       \
        cpa_commit();                                                           \
    }

    float oa[2][8][4];
#pragma unroll
    for (int t = 0; t < 2; t++)
#pragma unroll
        for (int j = 0; j < 8; j++)
#pragma unroll
            for (int v = 0; v < 4; v++) oa[t][j][v] = 0.f;
    float mx[2][2] = {{-INFINITY, -INFINITY}, {-INFINITY, -INFINITY}};
    float ll[2][2] = {{0.f, 0.f}, {0.f, 0.f}};

    const uint32_t* mr[2][2];
#pragma unroll
    for (int t = 0; t < 2; t++) {
        mr[t][0] = Mb + (size_t)(b * SEQ + q0 + t * 64 + warp * 16 + g) * (SEQ / 32);
        mr[t][1] = mr[t][0] + 8 * (SEQ / 32);
    }

    A_LOAD(0, 0);
    A_LOAD(1, 1);
    A_LOAD(2, 2);

    for (int kt = 0; kt < NKT; kt++) {
        if (kt < NKT - 2)       cpa_wait2();
        else if (kt == NKT - 2) cpa_wait1();
        else                    cpa_wait0();
        __syncthreads();
        if (kt + 3 < NKT) A_LOAD((kt + 3) & 3, kt + 3);

        const uint32_t sK = base + (uint32_t)(kt & 3) * ASTG;
        const uint32_t sV = sK + APLN;

        // S = Q K^T (log2 domain) for both subtiles, sharing K fragments.
        float s[2][8][4];
#pragma unroll
        for (int t = 0; t < 2; t++)
#pragma unroll
            for (int j = 0; j < 8; j++)
#pragma unroll
                for (int v = 0; v < 4; v++) s[t][j][v] = 0.f;
#pragma unroll
        for (int kk = 0; kk < 4; kk++) {
            uint32_t bh[4][4];
            const int bro = (lane & 7) + (lane >> 4) * 8;
            const int bco = kk * 16 + ((lane >> 3) & 1) * 8;
#pragma unroll
            for (int j2 = 0; j2 < 4; j2++)
                ldm4(bh[j2], sK + (uint32_t)(j2 * 16 + bro) * (LDA * 2) + bco * 2);
#pragma unroll
            for (int t = 0; t < 2; t++)
#pragma unroll
                for (int j = 0; j < 8; j++)
                    mma16816(s[t][j], qh[t][kk], &bh[j >> 1][(j & 1) * 2]);
        }

        // Mask + online softmax (log2 domain) + P repack per subtile.
        uint32_t ph[2][4][4];
#pragma unroll
        for (int t = 0; t < 2; t++) {
            uint32_t w0a = mr[t][0][kt * 2], w0b = mr[t][0][kt * 2 + 1];
            uint32_t w1a = mr[t][1][kt * 2], w1b = mr[t][1][kt * 2 + 1];
#pragma unroll
            for (int j = 0; j < 8; j++) {
                uint32_t wr0 = (j < 4) ? w0a : w0b;
                uint32_t wr1 = (j < 4) ? w1a : w1b;
                int sh = (j * 8 + t2) & 31;
                if (!((wr0 >> sh) & 1u))       s[t][j][0] = -1e20f;
                if (!((wr0 >> (sh + 1)) & 1u)) s[t][j][1] = -1e20f;
                if (!((wr1 >> sh) & 1u))       s[t][j][2] = -1e20f;
                if (!((wr1 >> (sh + 1)) & 1u)) s[t][j][3] = -1e20f;
            }

            float tm0 = s[t][0][0], tm1 = s[t][0][2];
#pragma unroll
            for (int j = 0; j < 8; j++) {
                tm0 = fmaxf(tm0, fmaxf(s[t][j][0], s[t][j][1]));
                tm1 = fmaxf(tm1, fmaxf(s[t][j][2], s[t][j][3]));
            }
            tm0 = fmaxf(tm0, __shfl_xor_sync(0xffffffffu, tm0, 1));
            tm0 = fmaxf(tm0, __shfl_xor_sync(0xffffffffu, tm0, 2));
            tm1 = fmaxf(tm1, __shfl_xor_sync(0xffffffffu, tm1, 1));
            tm1 = fmaxf(tm1, __shfl_xor_sync(0xffffffffu, tm1, 2));
            float nm0 = fmaxf(mx[t][0], tm0), nm1 = fmaxf(mx[t][1], tm1);
            float cr0 = ex2f(mx[t][0] - nm0), cr1 = ex2f(mx[t][1] - nm1);
            mx[t][0] = nm0; mx[t][1] = nm1;

            float ps0 = 0.f, ps1 = 0.f;
#pragma unroll
            for (int j = 0; j < 8; j++) {
                s[t][j][0] = ex2f(s[t][j][0] - nm0); ps0 += s[t][j][0];
                s[t][j][1] = ex2f(s[t][j][1] - nm0); ps0 += s[t][j][1];
                s[t][j][2] = ex2f(s[t][j][2] - nm1); ps1 += s[t][j][2];
                s[t][j][3] = ex2f(s[t][j][3] - nm1); ps1 += s[t][j][3];
            }
            ps0 += __shfl_xor_sync(0xffffffffu, ps0, 1);
            ps0 += __shfl_xor_sync(0xffffffffu, ps0, 2);
            ps1 += __shfl_xor_sync(0xffffffffu, ps1, 1);
            ps1 += __shfl_xor_sync(0xffffffffu, ps1, 2);
            ll[t][0] = ll[t][0] * cr0 + ps0;
            ll[t][1] = ll[t][1] * cr1 + ps1;
#pragma unroll
            for (int j = 0; j < 8; j++) {
                oa[t][j][0] *= cr0; oa[t][j][1] *= cr0;
                oa[t][j][2] *= cr1; oa[t][j][3] *= cr1;
            }
#pragma unroll
            for (int s4 = 0; s4 < 4; s4++) {
                int ta = 2 * s4, tb = ta + 1;
                ph[t][s4][0] = h2pack(s[t][ta][0], s[t][ta][1]);
                ph[t][s4][1] = h2pack(s[t][ta][2], s[t][ta][3]);
                ph[t][s4][2] = h2pack(s[t][tb][0], s[t][tb][1]);
                ph[t][s4][3] = h2pack(s[t][tb][2], s[t][tb][3]);
            }
        }

        // O += P V for both subtiles, sharing V fragments.
#pragma unroll
        for (int s4 = 0; s4 < 4; s4++) {
            uint32_t vh[4][4];
            const int vrow = s4 * 16 + ((lane >> 3) & 1) * 8 + (lane & 7);
#pragma unroll
            for (int n2 = 0; n2 < 4; n2++) {
                int vcol = n2 * 16 + (lane >> 4) * 8;
                ldm4t(vh[n2], sV + (uint32_t)vrow * (LDA * 2) + vcol * 2);
            }
#pragma unroll
            for (int t = 0; t < 2; t++)
#pragma unroll
                for (int j = 0; j < 8; j++)
                    mma16816(oa[t][j], ph[t][s4], &vh[j >> 1][(j & 1) * 2]);
        }
    }

#pragma unroll
    for (int t = 0; t < 2; t++) {
        float il0 = 1.f / ll[t][0], il1 = 1.f / ll[t][1];
        int row0 = b * SEQ + q0 + t * 64 + warp * 16 + g;
        size_t b0 = (size_t)row0 * DM + h * HD;
        size_t b1 = b0 + (size_t)8 * DM;
#pragma unroll
        for (int j = 0; j < 8; j++) {
            *(uint32_t*)(O + b0 + j * 8 + t2) = h2pack(oa[t][j][0] * il0, oa[t][j][1] * il0);
            *(uint32_t*)(O + b1 + j * 8 + t2) = h2pack(oa[t][j][2] * il1, oa[t][j][3] * il1);
        }
    }
#undef A_LOAD
}

// ---------------------------------------------------------------------------
extern "C" void kernel_launch(void* const* d_in, const int* in_sizes, int n_in,
                              void* d_out, int out_size) {
    const float* query = (const float*)d_in[0];
    const float* key_t = (const float*)d_in[1];
    const float* value = (const float*)d_in[2];
    const int*   mask  = (const int*)d_in[3];
    const float* wq    = (const float*)d_in[4];
    const float* wk    = (const float*)d_in[5];
    const float* wv    = (const float*)d_in[6];
    const float* wo    = (const float*)d_in[7];
    float* out = (float*)d_out;

    __half *iQ, *iK, *iV, *wqh, *wkh, *wvh, *woh, *Qp, *Kp, *Vp, *Op;
    uint32_t* Mb;
    cudaGetSymbolAddress((void**)&iQ, g_iQ);   cudaGetSymbolAddress((void**)&iK, g_iK);
    cudaGetSymbolAddress((void**)&iV, g_iV);
    cudaGetSymbolAddress((void**)&wqh, g_wq);  cudaGetSymbolAddress((void**)&wkh, g_wk);
    cudaGetSymbolAddress((void**)&wvh, g_wv);  cudaGetSymbolAddress((void**)&woh, g_wo);
    cudaGetSymbolAddress((void**)&Qp, g_Q);    cudaGetSymbolAddress((void**)&Kp, g_K);
    cudaGetSymbolAddress((void**)&Vp, g_V);    cudaGetSymbolAddress((void**)&Op, g_O);
    cudaGetSymbolAddress((void**)&Mb, g_Mb);

    static bool attr_set = false;
    if (!attr_set) {
        cudaFuncSetAttribute(gemm_proj, cudaFuncAttributeMaxDynamicSharedMemorySize, GDSM);
        cudaFuncSetAttribute(gemm_out,  cudaFuncAttributeMaxDynamicSharedMemorySize, GDSM);
        cudaFuncSetAttribute(attn_fp16, cudaFuncAttributeMaxDynamicSharedMemorySize, ADSM);
        attr_set = true;
    }

    prep_all<<<PREP_BLOCKS, 256>>>(query, key_t, value, wq, wk, wv, wo, mask,
                                   iQ, iK, iV, wqh, wkh, wvh, woh, Mb);

    dim3 gp3(DM / 128, NTOK / 128, 3);   // (8, 32, 3)
    gemm_proj<<<gp3, 128, GDSM>>>(iQ, iK, iV, wqh, wkh, wvh, Qp, Kp, Vp);

    dim3 ga(SEQ / 128, NH, BATCH);       // (16, 16, 2)
    attn_fp16<<<ga, 128, ADSM>>>(Qp, Kp, Vp, Mb, Op);

    dim3 gg(DM / 128, NTOK / 128);       // (8, 32)
    gemm_out<<<gg, 128, GDSM>>>(Op, woh, out);
}

// round 17
// speedup vs baseline: 1.0792x; 1.0223x over previous
#include <cuda_runtime.h>
#include <cuda_fp16.h>
#include <math.h>
#include <stdint.h>

#define DM   1024
#define HD   64
#define NH   16
#define BATCH 2
#define SEQ  2048
#define NTOK (BATCH*SEQ)
#define MWORDS (BATCH*SEQ*SEQ/32)

// ---------------------------------------------------------------------------
// Scratch (no allocations allowed).  Pure fp16 pipeline.
// ---------------------------------------------------------------------------
__device__ __half g_iQ[NTOK*DM], g_iK[NTOK*DM], g_iV[NTOK*DM];
__device__ __half g_wq[DM*DM], g_wk[DM*DM], g_wv[DM*DM], g_wo[DM*DM];
__device__ __half g_Q[NTOK*DM], g_K[NTOK*DM], g_V[NTOK*DM];
__device__ __half g_O[NTOK*DM];
__device__ uint32_t g_Mb[MWORDS];

// ---------------------------------------------------------------------------
// Helpers
// ---------------------------------------------------------------------------
__device__ __forceinline__ uint32_t smem_u32(const void* p) {
    uint32_t a;
    asm("{ .reg .u64 t; cvta.to.shared.u64 t, %1; cvt.u32.u64 %0, t; }" : "=r"(a) : "l"(p));
    return a;
}
__device__ __forceinline__ uint32_t h2pack(float lo, float hi) {
    __half2 t = __floats2half2_rn(lo, hi);
    return *reinterpret_cast<uint32_t*>(&t);
}
__device__ __forceinline__ float ex2f(float x) {
    float y;
    asm("ex2.approx.ftz.f32 %0, %1;" : "=f"(y) : "f"(x));
    return y;
}
__device__ __forceinline__ void ldm4(uint32_t* r, uint32_t addr) {
    asm volatile("ldmatrix.sync.aligned.m8n8.x4.shared.b16 {%0,%1,%2,%3}, [%4];"
                 : "=r"(r[0]), "=r"(r[1]), "=r"(r[2]), "=r"(r[3]) : "r"(addr));
}
__device__ __forceinline__ void ldm4t(uint32_t* r, uint32_t addr) {
    asm volatile("ldmatrix.sync.aligned.m8n8.x4.trans.shared.b16 {%0,%1,%2,%3}, [%4];"
                 : "=r"(r[0]), "=r"(r[1]), "=r"(r[2]), "=r"(r[3]) : "r"(addr));
}
__device__ __forceinline__ void mma16816(float* c, const uint32_t* a, const uint32_t* b) {
    asm volatile(
        "mma.sync.aligned.m16n8k16.row.col.f32.f16.f16.f32 "
        "{%0,%1,%2,%3}, {%4,%5,%6,%7}, {%8,%9}, {%0,%1,%2,%3};\n"
        : "+f"(c[0]), "+f"(c[1]), "+f"(c[2]), "+f"(c[3])
        : "r"(a[0]), "r"(a[1]), "r"(a[2]), "r"(a[3]), "r"(b[0]), "r"(b[1]));
}
__device__ __forceinline__ void cpa16(uint32_t dst, const void* src) {
    asm volatile("cp.async.cg.shared.global [%0], [%1], 16;" :: "r"(dst), "l"(src) : "memory");
}
__device__ __forceinline__ void cpa_commit() { asm volatile("cp.async.commit_group;" ::: "memory"); }
__device__ __forceinline__ void cpa_wait3()  { asm volatile("cp.async.wait_group 3;" ::: "memory"); }
__device__ __forceinline__ void cpa_wait2()  { asm volatile("cp.async.wait_group 2;" ::: "memory"); }
__device__ __forceinline__ void cpa_wait1()  { asm volatile("cp.async.wait_group 1;" ::: "memory"); }
__device__ __forceinline__ void cpa_wait0()  { asm volatile("cp.async.wait_group 0;" ::: "memory"); }

// ---------------------------------------------------------------------------
// Fused prep: 7 fp32->fp16 conversions (4 x float4 per thread, MLP=4)
// + mask bitpack, one launch.
// ---------------------------------------------------------------------------
#define IN_U  (NTOK*DM/4)            // 1048576 float4 units per input array
#define W_U   (DM*DM/4)              // 262144 per weight
#define CONV_UNITS (3*IN_U + 4*W_U)  // 4194304 (multiple of 4)
#define CONV_T (CONV_UNITS/4)        // 1048576 conv threads (mult of 256)
#define MASK_UNITS (BATCH*SEQ*SEQ/4) // 2097152 int4 units
#define PREP_BLOCKS ((CONV_T + MASK_UNITS) / 256)

__global__ __launch_bounds__(256) void prep_all(
    const float* __restrict__ q, const float* __restrict__ k,
    const float* __restrict__ v,
    const float* __restrict__ wq, const float* __restrict__ wk,
    const float* __restrict__ wv, const float* __restrict__ wo,
    const int* __restrict__ mask,
    __half* __restrict__ iQ, __half* __restrict__ iK, __half* __restrict__ iV,
    __half* __restrict__ wqh, __half* __restrict__ wkh,
    __half* __restrict__ wvh, __half* __restrict__ woh,
    uint32_t* __restrict__ bits) {
    int idx = blockIdx.x * 256 + threadIdx.x;
    if (idx < CONV_T) {
        int u0 = idx * 4;                 // first float4 unit of 4
        const float* src; __half* dst; int off;
        if (u0 < 3 * IN_U) {
            int arr = u0 >> 20;
            off = u0 & (IN_U - 1);
            src = arr == 0 ? q : arr == 1 ? k : v;
            dst = arr == 0 ? iQ : arr == 1 ? iK : iV;
        } else {
            int w = u0 - 3 * IN_U;
            int arr = w >> 18;
            off = w & (W_U - 1);
            src = arr == 0 ? wq : arr == 1 ? wk : arr == 2 ? wv : wo;
            dst = arr == 0 ? wqh : arr == 1 ? wkh : arr == 2 ? wvh : woh;
        }
        float4 a0 = ((const float4*)src)[off];
        float4 a1 = ((const float4*)src)[off + 1];
        float4 a2 = ((const float4*)src)[off + 2];
        float4 a3 = ((const float4*)src)[off + 3];
        ((uint2*)dst)[off]     = make_uint2(h2pack(a0.x, a0.y), h2pack(a0.z, a0.w));
        ((uint2*)dst)[off + 1] = make_uint2(h2pack(a1.x, a1.y), h2pack(a1.z, a1.w));
        ((uint2*)dst)[off + 2] = make_uint2(h2pack(a2.x, a2.y), h2pack(a2.z, a2.w));
        ((uint2*)dst)[off + 3] = make_uint2(h2pack(a3.x, a3.y), h2pack(a3.z, a3.w));
    } else {
        int t = idx - CONV_T;             // (t & 7) == (threadIdx.x & 7)
        int4 m = ((const int4*)mask)[t];
        uint32_t nib = (m.x != 0 ? 1u : 0u) | (m.y != 0 ? 2u : 0u) |
                       (m.z != 0 ? 4u : 0u) | (m.w != 0 ? 8u : 0u);
        uint32_t vv = nib << ((threadIdx.x & 7) * 4);
        vv |= __shfl_xor_sync(0xffffffffu, vv, 1);
        vv |= __shfl_xor_sync(0xffffffffu, vv, 2);
        vv |= __shfl_xor_sync(0xffffffffu, vv, 4);
        if ((threadIdx.x & 7) == 0) bits[t >> 3] = vv;
    }
}

// ---------------------------------------------------------------------------
// fp16 GEMM body (EXACT R10 champion config — frozen):
// Tile 128x128, BK=32, 5-stage cp.async pipeline, 4 warps (2m x 2n),
// warp tile 64x64 (32 MMAs per kk on 8 LDSM).
// MODE 1: fp16 C (scaled).  MODE 0: fp32 C.
// ---------------------------------------------------------------------------
#define LDSg 40                 // fp16 row stride (80B), conflict-free ldmatrix
#define PSTG (128*LDSg*2)       // 10240 B per plane
#define SSTG (2*PSTG)           // 20480 B per stage (A, B)
#define GNST 5
#define GDSM (GNST*SSTG)        // 102400 B dynamic smem

template<int MODE>
__device__ __forceinline__ void gemm_body(const __half* __restrict__ A,
                                          const __half* __restrict__ B,
                                          float* __restrict__ C,
                                          __half* __restrict__ Ch, float scale) {
    extern __shared__ char dsm[];
    const uint32_t base = smem_u32(dsm);
    const int tid = threadIdx.x, lane = tid & 31, warp = tid >> 5;
    const int wm = (warp & 1) * 64;
    const int wn = (warp >> 1) * 64;
    const int bm = blockIdx.y * 128;
    const int bn = blockIdx.x * 128;

    const __half* gp[2] = { A + (size_t)bm * DM, B + (size_t)bn * DM };

    float acc[4][8][4];
#pragma unroll
    for (int i = 0; i < 4; i++)
#pragma unroll
        for (int j = 0; j < 8; j++)
#pragma unroll
            for (int v = 0; v < 4; v++) acc[i][j][v] = 0.f;

    // Stage load: 2 planes x 128 rows x 4 x 16B chunks = 1024 chunks, 8/thread.
#define G_LOAD(s, k0)                                                           \
    {                                                                           \
        uint32_t sb = base + (uint32_t)(s) * SSTG;                              \
        _Pragma("unroll")                                                       \
        for (int i = 0; i < 8; i++) {                                           \
            int id = tid + i * 128;                                             \
            int pl = id >> 9, cid = id & 511;                                   \
            int r = cid >> 2, ch = cid & 3;                                     \
            cpa16(sb + pl * PSTG + r * (LDSg * 2) + ch * 16,                    \
                  gp[pl] + (size_t)r * DM + (k0) + ch * 8);                     \
        }                                                                       \
        cpa_commit();                                                           \
    }

    G_LOAD(0, 0);
    G_LOAD(1, 32);
    G_LOAD(2, 64);
    G_LOAD(3, 96);

    for (int kt = 0; kt < 32; kt++) {
        int rem = 31 - kt;
        if (rem >= 3)      cpa_wait3();
        else if (rem == 2) cpa_wait2();
        else if (rem == 1) cpa_wait1();
        else               cpa_wait0();
        __syncthreads();
        if (kt + 4 < 32) G_LOAD((kt + 4) % GNST, (kt + 4) * 32);

        const uint32_t sb = base + (uint32_t)(kt % GNST) * SSTG;
        const uint32_t sA = sb, sB = sb + PSTG;

#pragma unroll
        for (int kk = 0; kk < 2; kk++) {
            uint32_t ah[4][4], bh[4][4];
            const int acol = kk * 16 + (lane >> 4) * 8;
#pragma unroll
            for (int i = 0; i < 4; i++) {
                int arow = wm + i * 16 + (lane & 15);
                ldm4(ah[i], sA + (uint32_t)arow * (LDSg * 2) + acol * 2);
            }
            const int bcol = kk * 16 + ((lane >> 3) & 1) * 8;
            const int brow_off = (lane & 7) + (lane >> 4) * 8;
#pragma unroll
            for (int j2 = 0; j2 < 4; j2++) {
                int brow = wn + j2 * 16 + brow_off;
                ldm4(bh[j2], sB + (uint32_t)brow * (LDSg * 2) + bcol * 2);
            }
#pragma unroll
            for (int i = 0; i < 4; i++)
#pragma unroll
                for (int j = 0; j < 8; j++)
                    mma16816(acc[i][j], ah[i], &bh[j >> 1][(j & 1) * 2]);
        }
    }

    const int g  = lane >> 2;
    const int t2 = (lane & 3) * 2;
#pragma unroll
    for (int i = 0; i < 4; i++)
#pragma unroll
        for (int j = 0; j < 8; j++) {
            int row = bm + wm + i * 16 + g;
            int col = bn + wn + j * 8 + t2;
            size_t i0 = (size_t)row * DM + col;
            size_t i1 = (size_t)(row + 8) * DM + col;
            float v0 = acc[i][j][0] * scale, v1 = acc[i][j][1] * scale;
            float v2 = acc[i][j][2] * scale, v3 = acc[i][j][3] * scale;
            if (MODE == 0) {
                *(float2*)(C + i0) = make_float2(v0, v1);
                *(float2*)(C + i1) = make_float2(v2, v3);
            } else {
                *(uint32_t*)(Ch + i0) = h2pack(v0, v1);
                *(uint32_t*)(Ch + i1) = h2pack(v2, v3);
            }
        }
#undef G_LOAD
}

// Batched projection GEMM (z = 0:Q, 1:K, 2:V) and output GEMM.
// Q is pre-scaled by (1/8)*log2(e): attention scores land in the log2 domain,
// so softmax uses bare ex2.approx (no per-element FMUL by log2e).
__global__ __launch_bounds__(128, 2) void gemm_proj(
    const __half* __restrict__ iQ, const __half* __restrict__ iK,
    const __half* __restrict__ iV,
    const __half* __restrict__ wq, const __half* __restrict__ wk,
    const __half* __restrict__ wv,
    __half* __restrict__ Qo, __half* __restrict__ Ko, __half* __restrict__ Vo) {
    const __half* A; const __half* B; __half* Ch; float scale = 1.0f;
    if (blockIdx.z == 0)      { A = iQ; B = wq; Ch = Qo; scale = 0.125f * 1.44269504f; }
    else if (blockIdx.z == 1) { A = iK; B = wk; Ch = Ko; }
    else                      { A = iV; B = wv; Ch = Vo; }
    gemm_body<1>(A, B, nullptr, Ch, scale);
}
__global__ __launch_bounds__(128, 2) void gemm_out(
    const __half* __restrict__ O, const __half* __restrict__ wo,
    float* __restrict__ out) {
    gemm_body<0>(O, wo, out, nullptr, 1.0f);
}

// ---------------------------------------------------------------------------
// fp16 flash attention, ONLINE softmax in the log2 domain.
// vs R16: (a) ps quad-reduction deferred to the epilogue (cr is quad-uniform,
// so per-lane ll partials are exact); (b) rescale/correction skipped via a
// warp vote when no row max advanced (skipping a *1.0 is bit-exact).
// 128 q-rows per CTA, 4 warps, 4-stage cp.async K/V pipeline.
// ---------------------------------------------------------------------------
#define LDA 72                   // fp16 row stride (144B), conflict-free
#define APLN (64*LDA*2)          // 9216 B per plane
#define ASTG (2*APLN)            // 18432 B per stage (K, V)
#define ADSM (4*ASTG)            // 73728 B dynamic smem (4 stages)
#define NKT  (SEQ/64)            // 32

__global__ __launch_bounds__(128, 2) void attn_fp16(
    const __half* __restrict__ Q, const __half* __restrict__ K,
    const __half* __restrict__ V, const uint32_t* __restrict__ Mb,
    __half* __restrict__ O) {
    extern __shared__ char dsm[];
    const uint32_t base = smem_u32(dsm);

    const int b = blockIdx.z, h = blockIdx.y;
    const int q0 = blockIdx.x * 128;
    const int tid = threadIdx.x, lane = tid & 31, warp = tid >> 5;
    const int g = lane >> 2, t2 = (lane & 3) * 2;

    {
        __half* sQ = (__half*)(dsm);
        for (int idx = tid; idx < 1024; idx += 128) {
            int r = idx >> 3, c = (idx & 7) * 8;
            size_t go = (size_t)(b * SEQ + q0 + r) * DM + h * HD + c;
            *(uint4*)(sQ + r * LDA + c) = *(const uint4*)(Q + go);
        }
    }
    __syncthreads();
    uint32_t qh[2][4][4];
#pragma unroll
    for (int t = 0; t < 2; t++) {
        int arow = t * 64 + warp * 16 + (lane & 15);
#pragma unroll
        for (int kk = 0; kk < 4; kk++) {
            int acol = kk * 16 + (lane >> 4) * 8;
            ldm4(qh[t][kk], base + (uint32_t)arow * (LDA * 2) + acol * 2);
        }
    }
    __syncthreads();

#define A_LOAD(s, kt)                                                           \
    {                                                                           \
        uint32_t sb = base + (uint32_t)(s) * ASTG;                              \
        const __half* gsrc[2] = { K, V };                                       \
        _Pragma("unroll")                                                       \
        for (int i = 0; i < 8; i++) {                                           \
            int id = tid + i * 128;                                             \
            int ar = id >> 9, cid = id & 511;                                   \
            int r = cid >> 3, ch = cid & 7;                                     \
            cpa16(sb + ar * APLN + r * (LDA * 2) + ch * 16,                     \
                  gsrc[ar] + (size_t)(b * SEQ + (kt) * 64 + r) * DM + h * HD + ch * 8); \
        }                                                                       \
        cpa_commit();                                                           \
    }

    float oa[2][8][4];
#pragma unroll
    for (int t = 0; t < 2; t++)
#pragma unroll
        for (int j = 0; j < 8; j++)
#pragma unroll
            for (int v = 0; v < 4; v++) oa[t][j][v] = 0.f;
    float mx[2][2] = {{-INFINITY, -INFINITY}, {-INFINITY, -INFINITY}};
    float ll[2][2] = {{0.f, 0.f}, {0.f, 0.f}};   // per-lane partials

    const uint32_t* mr[2][2];
#pragma unroll
    for (int t = 0; t < 2; t++) {
        mr[t][0] = Mb + (size_t)(b * SEQ + q0 + t * 64 + warp * 16 + g) * (SEQ / 32);
        mr[t][1] = mr[t][0] + 8 * (SEQ / 32);
    }

    A_LOAD(0, 0);
    A_LOAD(1, 1);
    A_LOAD(2, 2);

    for (int kt = 0; kt < NKT; kt++) {
        if (kt < NKT - 2)       cpa_wait2();
        else if (kt == NKT - 2) cpa_wait1();
        else                    cpa_wait0();
        __syncthreads();
        if (kt + 3 < NKT) A_LOAD((kt + 3) & 3, kt + 3);

        const uint32_t sK = base + (uint32_t)(kt & 3) * ASTG;
        const uint32_t sV = sK + APLN;

        // S = Q K^T (log2 domain) for both subtiles, sharing K fragments.
        float s[2][8][4];
#pragma unroll
        for (int t = 0; t < 2; t++)
#pragma unroll
            for (int j = 0; j < 8; j++)
#pragma unroll
                for (int v = 0; v < 4; v++) s[t][j][v] = 0.f;
#pragma unroll
        for (int kk = 0; kk < 4; kk++) {
            uint32_t bh[4][4];
            const int bro = (lane & 7) + (lane >> 4) * 8;
            const int bco = kk * 16 + ((lane >> 3) & 1) * 8;
#pragma unroll
            for (int j2 = 0; j2 < 4; j2++)
                ldm4(bh[j2], sK + (uint32_t)(j2 * 16 + bro) * (LDA * 2) + bco * 2);
#pragma unroll
            for (int t = 0; t < 2; t++)
#pragma unroll
                for (int j = 0; j < 8; j++)
                    mma16816(s[t][j], qh[t][kk], &bh[j >> 1][(j & 1) * 2]);
        }

        // Mask + online softmax (log2 domain) + P repack per subtile.
        uint32_t ph[2][4][4];
#pragma unroll
        for (int t = 0; t < 2; t++) {
            uint32_t w0a = mr[t][0][kt * 2], w0b = mr[t][0][kt * 2 + 1];
            uint32_t w1a = mr[t][1][kt * 2], w1b = mr[t][1][kt * 2 + 1];
#pragma unroll
            for (int j = 0; j < 8; j++) {
                uint32_t wr0 = (j < 4) ? w0a : w0b;
                uint32_t wr1 = (j < 4) ? w1a : w1b;
                int sh = (j * 8 + t2) & 31;
                if (!((wr0 >> sh) & 1u))       s[t][j][0] = -1e20f;
                if (!((wr0 >> (sh + 1)) & 1u)) s[t][j][1] = -1e20f;
                if (!((wr1 >> sh) & 1u))       s[t][j][2] = -1e20f;
                if (!((wr1 >> (sh + 1)) & 1u)) s[t][j][3] = -1e20f;
            }

            float tm0 = s[t][0][0], tm1 = s[t][0][2];
#pragma unroll
            for (int j = 0; j < 8; j++) {
                tm0 = fmaxf(tm0, fmaxf(s[t][j][0], s[t][j][1]));
                tm1 = fmaxf(tm1, fmaxf(s[t][j][2], s[t][j][3]));
            }
            tm0 = fmaxf(tm0, __shfl_xor_sync(0xffffffffu, tm0, 1));
            tm0 = fmaxf(tm0, __shfl_xor_sync(0xffffffffu, tm0, 2));
            tm1 = fmaxf(tm1, __shfl_xor_sync(0xffffffffu, tm1, 1));
            tm1 = fmaxf(tm1, __shfl_xor_sync(0xffffffffu, tm1, 2));
            float nm0 = fmaxf(mx[t][0], tm0), nm1 = fmaxf(mx[t][1], tm1);

            // Rescale only when some row max advanced (skipping *1.0 is exact).
            bool upd = (tm0 > mx[t][0]) || (tm1 > mx[t][1]);
            if (__any_sync(0xffffffffu, upd)) {
                float cr0 = ex2f(mx[t][0] - nm0), cr1 = ex2f(mx[t][1] - nm1);
                ll[t][0] *= cr0; ll[t][1] *= cr1;
#pragma unroll
                for (int j = 0; j < 8; j++) {
                    oa[t][j][0] *= cr0; oa[t][j][1] *= cr0;
                    oa[t][j][2] *= cr1; oa[t][j][3] *= cr1;
                }
            }
            mx[t][0] = nm0; mx[t][1] = nm1;

            float ps0 = 0.f, ps1 = 0.f;
#pragma unroll
            for (int j = 0; j < 8; j++) {
                s[t][j][0] = ex2f(s[t][j][0] - nm0); ps0 += s[t][j][0];
                s[t][j][1] = ex2f(s[t][j][1] - nm0); ps0 += s[t][j][1];
                s[t][j][2] = ex2f(s[t][j][2] - nm1); ps1 += s[t][j][2];
                s[t][j][3] = ex2f(s[t][j][3] - nm1); ps1 += s[t][j][3];
            }
            ll[t][0] += ps0;            // per-lane partial; quad-reduced at end
            ll[t][1] += ps1;
#pragma unroll
            for (int s4 = 0; s4 < 4; s4++) {
                int ta = 2 * s4, tb = ta + 1;
                ph[t][s4][0] = h2pack(s[t][ta][0], s[t][ta][1]);
                ph[t][s4][1] = h2pack(s[t][ta][2], s[t][ta][3]);
                ph[t][s4][2] = h2pack(s[t][tb][0], s[t][tb][1]);
                ph[t][s4][3] = h2pack(s[t][tb][2], s[t][tb][3]);
            }
        }

        // O += P V for both subtiles, sharing V fragments.
#pragma unroll
        for (int s4 = 0; s4 < 4; s4++) {
            uint32_t vh[4][4];
            const int vrow = s4 * 16 + ((lane >> 3) & 1) * 8 + (lane & 7);
#pragma unroll
            for (int n2 = 0; n2 < 4; n2++) {
                int vcol = n2 * 16 + (lane >> 4) * 8;
                ldm4t(vh[n2], sV + (uint32_t)vrow * (LDA * 2) + vcol * 2);
            }
#pragma unroll
            for (int t = 0; t < 2; t++)
#pragma unroll
                for (int j = 0; j < 8; j++)
                    mma16816(oa[t][j], ph[t][s4], &vh[j >> 1][(j & 1) * 2]);
        }
    }

    // Final quad-reduction of ll partials (cr factors were quad-uniform).
#pragma unroll
    for (int t = 0; t < 2; t++) {
        ll[t][0] += __shfl_xor_sync(0xffffffffu, ll[t][0], 1);
        ll[t][0] += __shfl_xor_sync(0xffffffffu, ll[t][0], 2);
        ll[t][1] += __shfl_xor_sync(0xffffffffu, ll[t][1], 1);
        ll[t][1] += __shfl_xor_sync(0xffffffffu, ll[t][1], 2);
    }

#pragma unroll
    for (int t = 0; t < 2; t++) {
        float il0 = 1.f / ll[t][0], il1 = 1.f / ll[t][1];
        int row0 = b * SEQ + q0 + t * 64 + warp * 16 + g;
        size_t b0 = (size_t)row0 * DM + h * HD;
        size_t b1 = b0 + (size_t)8 * DM;
#pragma unroll
        for (int j = 0; j < 8; j++) {
            *(uint32_t*)(O + b0 + j * 8 + t2) = h2pack(oa[t][j][0] * il0, oa[t][j][1] * il0);
            *(uint32_t*)(O + b1 + j * 8 + t2) = h2pack(oa[t][j][2] * il1, oa[t][j][3] * il1);
        }
    }
#undef A_LOAD
}

// ---------------------------------------------------------------------------
extern "C" void kernel_launch(void* const* d_in, const int* in_sizes, int n_in,
                              void* d_out, int out_size) {
    const float* query = (const float*)d_in[0];
    const float* key_t = (const float*)d_in[1];
    const float* value = (const float*)d_in[2];
    const int*   mask  = (const int*)d_in[3];
    const float* wq    = (const float*)d_in[4];
    const float* wk    = (const float*)d_in[5];
    const float* wv    = (const float*)d_in[6];
    const float* wo    = (const float*)d_in[7];
    float* out = (float*)d_out;

    __half *iQ, *iK, *iV, *wqh, *wkh, *wvh, *woh, *Qp, *Kp, *Vp, *Op;
    uint32_t* Mb;
    cudaGetSymbolAddress((void**)&iQ, g_iQ);   cudaGetSymbolAddress((void**)&iK, g_iK);
    cudaGetSymbolAddress((void**)&iV, g_iV);
    cudaGetSymbolAddress((void**)&wqh, g_wq);  cudaGetSymbolAddress((void**)&wkh, g_wk);
    cudaGetSymbolAddress((void**)&wvh, g_wv);  cudaGetSymbolAddress((void**)&woh, g_wo);
    cudaGetSymbolAddress((void**)&Qp, g_Q);    cudaGetSymbolAddress((void**)&Kp, g_K);
    cudaGetSymbolAddress((void**)&Vp, g_V);    cudaGetSymbolAddress((void**)&Op, g_O);
    cudaGetSymbolAddress((void**)&Mb, g_Mb);

    static bool attr_set = false;
    if (!attr_set) {
        cudaFuncSetAttribute(gemm_proj, cudaFuncAttributeMaxDynamicSharedMemorySize, GDSM);
        cudaFuncSetAttribute(gemm_out,  cudaFuncAttributeMaxDynamicSharedMemorySize, GDSM);
        cudaFuncSetAttribute(attn_fp16, cudaFuncAttributeMaxDynamicSharedMemorySize, ADSM);
        attr_set = true;
    }

    prep_all<<<PREP_BLOCKS, 256>>>(query, key_t, value, wq, wk, wv, wo, mask,
                                   iQ, iK, iV, wqh, wkh, wvh, woh, Mb);

    dim3 gp3(DM / 128, NTOK / 128, 3);   // (8, 32, 3)
    gemm_proj<<<gp3, 128, GDSM>>>(iQ, iK, iV, wqh, wkh, wvh, Qp, Kp, Vp);

    dim3 ga(SEQ / 128, NH, BATCH);       // (16, 16, 2)
    attn_fp16<<<ga, 128, ADSM>>>(Qp, Kp, Vp, Mb, Op);

    dim3 gg(DM / 128, NTOK / 128);       // (8, 32)
    gemm_out<<<gg, 128, GDSM>>>(Op, woh, out);
}